// round 9
// baseline (speedup 1.0000x reference)
#include <cuda_runtime.h>
#include <cstdint>

// IntraLoss: loss = (1/N) * sum_n || features[n] - center[labels[n]] ||_2
// N=32768, C=1000, D=512. features f32 [N,D], labels int32 [N], center f32 [C,D].
//
// 2048 blocks x 128 threads. Block owns 16 contiguous rows (32KB features),
// fetched as 4 chunks x 8KB via cp.async.bulk into 4 distinct SMEM buffers
// (all issued at t=0, one mbarrier each, no reuse, no inter-stage syncs).
// 4 warps compute one row each per chunk; centers via __ldg (L2/L1-hot).
// Last block folds the 2048 partials.

#define NROWS 32768
#define NCLS  1000
#define DDIM  512
#define ROWS_PER_BLK 16
#define NBLK  (NROWS / ROWS_PER_BLK)      // 2048
#define NCHUNK 4
#define ROWS_PER_CHUNK 4                  // one row per warp
#define CHUNK_BYTES (ROWS_PER_CHUNK * DDIM * 4)   // 8192

__device__ float g_partials[NBLK];
__device__ unsigned int g_counter = 0;

__device__ __forceinline__ uint32_t s2u(const void* p) {
    return (uint32_t)__cvta_generic_to_shared(p);
}
__device__ __forceinline__ void mbar_init(uint32_t mbar, uint32_t count) {
    asm volatile("mbarrier.init.shared.b64 [%0], %1;" :: "r"(mbar), "r"(count) : "memory");
}
__device__ __forceinline__ void mbar_expect_tx(uint32_t mbar, uint32_t bytes) {
    asm volatile("mbarrier.arrive.expect_tx.shared.b64 _, [%0], %1;"
                 :: "r"(mbar), "r"(bytes) : "memory");
}
__device__ __forceinline__ void bulk_copy_g2s(uint32_t dst, const void* src,
                                              uint32_t bytes, uint32_t mbar) {
    asm volatile(
        "cp.async.bulk.shared::cta.global.mbarrier::complete_tx::bytes [%0], [%1], %2, [%3];"
        :: "r"(dst), "l"(src), "r"(bytes), "r"(mbar) : "memory");
}
__device__ __forceinline__ void mbar_wait0(uint32_t mbar) {
    asm volatile(
        "{\n\t.reg .pred P;\n\t"
        "W_%=: mbarrier.try_wait.parity.acquire.cta.shared::cta.b64 P, [%0], 0, 0x989680;\n\t"
        "@P bra.uni D_%=;\n\t"
        "bra.uni W_%=;\n\t"
        "D_%=:\n\t}"
        :: "r"(mbar) : "memory");
}

__global__ __launch_bounds__(128) void intra_loss_kernel(
    const float* __restrict__ feats,     // [N, D]
    const int* __restrict__ labels,      // [N]
    const float4* __restrict__ center,   // [C, D/4]
    float* __restrict__ out)
{
    __shared__ alignas(128) char sbuf[NCHUNK][CHUNK_BYTES];
    __shared__ alignas(8) unsigned long long mbar_store[NCHUNK];
    __shared__ float wpart[4];
    __shared__ bool is_last;

    const int tid  = threadIdx.x;
    const int lane = tid & 31;
    const int w    = tid >> 5;                    // warp 0..3
    const int base = blockIdx.x * ROWS_PER_BLK;

    uint32_t mb[NCHUNK];
    #pragma unroll
    for (int c = 0; c < NCHUNK; c++) mb[c] = s2u(&mbar_store[c]);

    if (tid == 0) {
        #pragma unroll
        for (int c = 0; c < NCHUNK; c++) mbar_init(mb[c], 1);
    }
    __syncthreads();

    if (tid == 0) {
        #pragma unroll
        for (int c = 0; c < NCHUNK; c++) {
            mbar_expect_tx(mb[c], CHUNK_BYTES);
            bulk_copy_g2s(s2u(&sbuf[c][0]),
                          feats + (size_t)(base + c * ROWS_PER_CHUNK) * DDIM,
                          CHUNK_BYTES, mb[c]);
        }
    }

    // Prefetch labels: warp w handles row base + c*4 + w for each chunk c.
    int lbl[NCHUNK];
    #pragma unroll
    for (int c = 0; c < NCHUNK; c++) {
        int v = __ldg(&labels[base + c * ROWS_PER_CHUNK + w]);
        lbl[c] = min(max(v, 0), NCLS - 1);
    }

    float dsum = 0.0f;

    #pragma unroll
    for (int c = 0; c < NCHUNK; c++) {
        mbar_wait0(mb[c]);

        const float4* srow = (const float4*)(&sbuf[c][w * (DDIM * 4)]);
        const float4* cr   = center + (size_t)lbl[c] * (DDIM / 4) + lane;

        float acc = 0.0f;
        #pragma unroll
        for (int i = 0; i < 4; i++) {
            float4 a = srow[lane + 32 * i];
            float4 b = __ldg(cr + 32 * i);
            float dx = a.x - b.x;
            float dy = a.y - b.y;
            float dz = a.z - b.z;
            float dw = a.w - b.w;
            acc = fmaf(dx, dx, acc);
            acc = fmaf(dy, dy, acc);
            acc = fmaf(dz, dz, acc);
            acc = fmaf(dw, dw, acc);
        }

        #pragma unroll
        for (int sh = 16; sh > 0; sh >>= 1)
            acc += __shfl_xor_sync(0xffffffffu, acc, sh);
        if (lane == 0) dsum += sqrtf(acc);
    }

    if (lane == 0) wpart[w] = dsum;
    __syncthreads();

    if (tid == 0) {
        float s = wpart[0] + wpart[1] + wpart[2] + wpart[3];
        g_partials[blockIdx.x] = s;
        __threadfence();
        unsigned int old = atomicAdd(&g_counter, 1u);
        is_last = (old == NBLK - 1);
    }
    __syncthreads();

    if (is_last) {
        float v = 0.0f;
        #pragma unroll
        for (int i = 0; i < NBLK / 128; i++)      // 16 each
            v += g_partials[tid + i * 128];

        #pragma unroll
        for (int sh = 16; sh > 0; sh >>= 1)
            v += __shfl_xor_sync(0xffffffffu, v, sh);

        if (lane == 0) wpart[w] = v;
        __syncthreads();

        if (tid == 0) {
            float t = wpart[0] + wpart[1] + wpart[2] + wpart[3];
            out[0] = t * (1.0f / (float)NROWS);
            g_counter = 0;   // reset for next graph replay
        }
    }
}

extern "C" void kernel_launch(void* const* d_in, const int* in_sizes, int n_in,
                              void* d_out, int out_size)
{
    const float* feats   = (const float*)d_in[0];
    const int* labels    = (const int*)d_in[1];
    const float4* center = (const float4*)d_in[2];
    float* out           = (float*)d_out;

    intra_loss_kernel<<<NBLK, 128>>>(feats, labels, center, out);
}

// round 10
// speedup vs baseline: 1.3163x; 1.3163x over previous
#include <cuda_runtime.h>

// IntraLoss: loss = (1/N) * sum_n || features[n] - center[labels[n]] ||_2
// N=32768, C=1000, D=512. features f32 [N,D], labels int32 [N], center f32 [C,D].
//
// R4 structure with the register ceiling lifted: __launch_bounds__(256, 4)
// gives a 64-reg budget so 4+4 float4 loads can actually be batched in
// registers (true MLP ~8 per thread). 1024 blocks x 256 threads, 8 warps,
// 4 rows/warp, 8 lanes/row. Last block folds the partials.

#define NROWS 32768
#define NCLS  1000
#define DDIM  512
#define NBLK  1024

__device__ float g_partials[NBLK];
__device__ unsigned int g_counter = 0;

__global__ __launch_bounds__(256, 4) void intra_loss_kernel(
    const float4* __restrict__ feats,    // [N, D/4]
    const int* __restrict__ labels,      // [N] int32
    const float4* __restrict__ center,   // [C, D/4]
    float* __restrict__ out)
{
    const int lane  = threadIdx.x & 31;
    const int wib   = threadIdx.x >> 5;                      // 0..7
    const int warpG = (blockIdx.x << 3) + wib;               // 0..8191
    const int g     = lane >> 3;                             // group 0..3
    const int l     = lane & 7;                              // lane in group
    const int row   = (warpG << 2) + g;                      // 4 rows per warp

    int lbl = labels[row];
    lbl = min(max(lbl, 0), NCLS - 1);

    const float4* fr = feats  + (size_t)row * (DDIM / 4) + l;
    const float4* cr = center + (size_t)lbl * (DDIM / 4) + l;

    float acc0 = 0.0f, acc1 = 0.0f;

    #pragma unroll
    for (int j = 0; j < 4; j++) {
        // 8 independent LDG.128 issued before any dependent FMA.
        float4 A0 = fr[(4 * j + 0) * 8];
        float4 A1 = fr[(4 * j + 1) * 8];
        float4 A2 = fr[(4 * j + 2) * 8];
        float4 A3 = fr[(4 * j + 3) * 8];
        float4 B0 = cr[(4 * j + 0) * 8];
        float4 B1 = cr[(4 * j + 1) * 8];
        float4 B2 = cr[(4 * j + 2) * 8];
        float4 B3 = cr[(4 * j + 3) * 8];

        float d;
        d = A0.x - B0.x; acc0 = fmaf(d, d, acc0);
        d = A0.y - B0.y; acc1 = fmaf(d, d, acc1);
        d = A0.z - B0.z; acc0 = fmaf(d, d, acc0);
        d = A0.w - B0.w; acc1 = fmaf(d, d, acc1);
        d = A1.x - B1.x; acc0 = fmaf(d, d, acc0);
        d = A1.y - B1.y; acc1 = fmaf(d, d, acc1);
        d = A1.z - B1.z; acc0 = fmaf(d, d, acc0);
        d = A1.w - B1.w; acc1 = fmaf(d, d, acc1);
        d = A2.x - B2.x; acc0 = fmaf(d, d, acc0);
        d = A2.y - B2.y; acc1 = fmaf(d, d, acc1);
        d = A2.z - B2.z; acc0 = fmaf(d, d, acc0);
        d = A2.w - B2.w; acc1 = fmaf(d, d, acc1);
        d = A3.x - B3.x; acc0 = fmaf(d, d, acc0);
        d = A3.y - B3.y; acc1 = fmaf(d, d, acc1);
        d = A3.z - B3.z; acc0 = fmaf(d, d, acc0);
        d = A3.w - B3.w; acc1 = fmaf(d, d, acc1);
    }

    float acc = acc0 + acc1;

    // reduce within 8-lane group (all 4 rows in parallel)
    acc += __shfl_xor_sync(0xffffffffu, acc, 1);
    acc += __shfl_xor_sync(0xffffffffu, acc, 2);
    acc += __shfl_xor_sync(0xffffffffu, acc, 4);

    // one sqrt per row (group leaders), zeros elsewhere
    float dres = (l == 0) ? sqrtf(acc) : 0.0f;

    // sum the 4 row-distances across groups
    dres += __shfl_xor_sync(0xffffffffu, dres, 8);
    dres += __shfl_xor_sync(0xffffffffu, dres, 16);

    __shared__ float smem[8];
    __shared__ bool is_last;
    if (lane == 0) smem[wib] = dres;
    __syncthreads();

    if (threadIdx.x == 0) {
        float s = 0.0f;
        #pragma unroll
        for (int i = 0; i < 8; i++) s += smem[i];
        g_partials[blockIdx.x] = s;
        __threadfence();
        unsigned int old = atomicAdd(&g_counter, 1u);
        is_last = (old == NBLK - 1);
    }
    __syncthreads();

    if (is_last) {
        float v = 0.0f;
        #pragma unroll
        for (int i = 0; i < 4; i++)
            v += g_partials[threadIdx.x + i * 256];

        #pragma unroll
        for (int s = 16; s > 0; s >>= 1)
            v += __shfl_xor_sync(0xffffffffu, v, s);

        __shared__ float smem2[8];
        if (lane == 0) smem2[wib] = v;
        __syncthreads();

        if (threadIdx.x == 0) {
            float w = 0.0f;
            #pragma unroll
            for (int i = 0; i < 8; i++) w += smem2[i];
            out[0] = w * (1.0f / (float)NROWS);
            g_counter = 0;   // reset for next graph replay
        }
    }
}

extern "C" void kernel_launch(void* const* d_in, const int* in_sizes, int n_in,
                              void* d_out, int out_size)
{
    const float4* feats  = (const float4*)d_in[0];
    const int* labels    = (const int*)d_in[1];
    const float4* center = (const float4*)d_in[2];
    float* out           = (float*)d_out;

    intra_loss_kernel<<<NBLK, 256>>>(feats, labels, center, out);
}